// round 6
// baseline (speedup 1.0000x reference)
#include <cuda_runtime.h>

// ---------------------------------------------------------------------------
// TypeGAT HICS, inverted formulation, v6.
//
//  k_scan : per-block SMEM hash (node -> entity); grid-stride int4 pass over
//           edges; hits push ONE fused 16B record {packed key, edge type}.
//  k_agg  : PDL-launched; ONE WARP PER ENTITY. Single parallel load round
//           (candidates + counters), shfl-rank top-k in registers, float4
//           gather/sum over query_weight, float4 store. Counters reset.
//
// Key packing preserves lax.top_k ordering: time desc, edge index asc.
// ---------------------------------------------------------------------------

#define MAX_B       4096
#define CAP         64
#define MAX_NODES   (1 << 20)
#define MAXK        32
#define HASH_SLOTS  4096
#define HASH_MASK   (HASH_SLOTS - 1)
#define EMPTY       0xFFFFFFFFu

__device__ int        g_cnt[2 * MAX_B];                 // [2b]=inc,[2b+1]=out; zero at load, k_agg restores
__device__ ulonglong2 g_cand_inc[(size_t)MAX_B * CAP];  // {key, type}
__device__ ulonglong2 g_cand_out[(size_t)MAX_B * CAP];

__device__ __forceinline__ unsigned int hash_node(unsigned int node) {
    return (node * 2654435761u) >> 20;   // top 12 bits -> [0, 4096)
}

// Orderable key: (monotone float bits << 32) | ~edge_index.
// Max key == (largest time, smallest index) — matches lax.top_k tie-break.
// Valid keys are nonzero (sign-flip bit set for finite non-negative time).
__device__ __forceinline__ unsigned long long pack_key(float t, unsigned int e) {
    unsigned int tb = __float_as_uint(t);
    tb = (tb & 0x80000000u) ? ~tb : (tb | 0x80000000u);
    return ((unsigned long long)tb << 32) | (unsigned long long)(~e);
}

__device__ __forceinline__ bool probe_any(const unsigned int* s_tab, unsigned int node) {
    if (node >= (unsigned int)MAX_NODES) return false;
    unsigned int h = hash_node(node), v;
    while ((v = s_tab[h]) != EMPTY) {
        if ((v >> 12) == node) return true;
        h = (h + 1) & HASH_MASK;
    }
    return false;
}

__device__ __forceinline__ void probe_push(const unsigned int* s_tab, unsigned int node,
                                           unsigned long long key, int etype, int dir,
                                           ulonglong2* __restrict__ cand) {
    unsigned int h = hash_node(node), v;
    while ((v = s_tab[h]) != EMPTY) {
        if ((v >> 12) == node) {
            int b = (int)(v & 0xFFFu);
            int p = atomicAdd(&g_cnt[2 * b + dir], 1);
            if (p < CAP)
                cand[(size_t)b * CAP + p] = make_ulonglong2(key, (unsigned long long)(unsigned int)etype);
        }
        h = (h + 1) & HASH_MASK;
    }
}

// ---------------------------------------------------------------------------
// Kernel 1: edge scan with per-block SMEM hash.
// ---------------------------------------------------------------------------
__global__ void k_scan(const int* __restrict__ src, const int* __restrict__ dst,
                       const int* __restrict__ etypes,
                       const float* __restrict__ times, int E,
                       const int* __restrict__ ent, int B,
                       const int* __restrict__ nn_ptr) {
    __shared__ unsigned int s_tab[HASH_SLOTS];
    for (int i = threadIdx.x; i < HASH_SLOTS; i += blockDim.x) s_tab[i] = EMPTY;
    __syncthreads();

    int nn = nn_ptr[0];
    if (nn > MAX_NODES) nn = MAX_NODES;
    for (int b = threadIdx.x; b < B && b < MAX_B; b += blockDim.x) {
        int node = ent[b];
        if (node >= 0 && node < nn) {
            unsigned int val = ((unsigned int)node << 12) | (unsigned int)b;
            unsigned int h = hash_node((unsigned int)node);
            while (atomicCAS(&s_tab[h], EMPTY, val) != EMPTY) h = (h + 1) & HASH_MASK;
        }
    }
    __syncthreads();

    int tid    = blockIdx.x * blockDim.x + threadIdx.x;
    int stride = gridDim.x * blockDim.x;
    int E4     = E >> 2;
    const int4* src4 = (const int4*)src;
    const int4* dst4 = (const int4*)dst;

    for (int i = tid; i < E4; i += stride) {
        int4 d4 = dst4[i];
        int4 s4 = src4[i];
        int e0 = i << 2;
#pragma unroll
        for (int j = 0; j < 4; ++j) {
            unsigned int d = (unsigned int)((j == 0) ? d4.x : (j == 1) ? d4.y : (j == 2) ? d4.z : d4.w);
            unsigned int s = (unsigned int)((j == 0) ? s4.x : (j == 1) ? s4.y : (j == 2) ? s4.z : s4.w);
            bool hd = probe_any(s_tab, d);
            bool hs = probe_any(s_tab, s);
            if (hd | hs) {
                int e = e0 + j;
                unsigned long long key = pack_key(times[e], (unsigned int)e);
                int ty = etypes[e];
                if (hd) probe_push(s_tab, d, key, ty, 0, g_cand_inc);
                if (hs) probe_push(s_tab, s, key, ty, 1, g_cand_out);
            }
        }
    }
    for (int e = (E4 << 2) + tid; e < E; e += stride) {
        unsigned int d = (unsigned int)dst[e];
        unsigned int s = (unsigned int)src[e];
        bool hd = probe_any(s_tab, d);
        bool hs = probe_any(s_tab, s);
        if (hd | hs) {
            unsigned long long key = pack_key(times[e], (unsigned int)e);
            int ty = etypes[e];
            if (hd) probe_push(s_tab, d, key, ty, 0, g_cand_inc);
            if (hs) probe_push(s_tab, s, key, ty, 1, g_cand_out);
        }
    }
}

// Fallback exact top-`take` for n > 32: iterative warp-max over the row.
__device__ __forceinline__ void warp_select_big(const ulonglong2* __restrict__ row,
                                                int n, int take,
                                                int* s_types, int off, int lane) {
    unsigned long long thresh = ~0ull;
    for (int r = 0; r < take; ++r) {
        unsigned long long bk = 0ull; int bt = 0;
        for (int i = lane; i < n && i < CAP; i += 32) {
            ulonglong2 c = row[i];
            if (c.x < thresh && c.x > bk) { bk = c.x; bt = (int)c.y; }
        }
#pragma unroll
        for (int o = 16; o; o >>= 1) {
            unsigned long long ok = __shfl_xor_sync(0xffffffffu, bk, o);
            int                ot = __shfl_xor_sync(0xffffffffu, bt, o);
            if (ok > bk) { bk = ok; bt = ot; }
        }
        if (lane == 0) s_types[off + r] = bt;
        thresh = bk;
    }
}

// ---------------------------------------------------------------------------
// Kernel 2: one warp per entity. PDL-aware.
// ---------------------------------------------------------------------------
__global__ void __launch_bounds__(256)
k_agg(const float* __restrict__ qw, float* __restrict__ out, int B, int D,
      const int* __restrict__ k_ptr) {
    __shared__ int s_types[8][MAXK];

    int lane = threadIdx.x & 31;
    int wl   = threadIdx.x >> 5;                       // warp in block
    int b    = blockIdx.x * 8 + wl;                    // entity

    // Prologue: harness inputs only.
    int k = k_ptr[0];
    if (k > MAXK) k = MAXK;
    if (k < 0)    k = 0;
    int kh = k >> 1;

    cudaGridDependencySynchronize();
    if (b >= B || b >= MAX_B) return;

    // --- one parallel load round: candidates + counters --------------------
    ulonglong2 ci = g_cand_inc[(size_t)b * CAP + lane];
    ulonglong2 co = g_cand_out[(size_t)b * CAP + lane];
    int2 cc = ((const int2*)g_cnt)[b];
    int cin = cc.x, cout = cc.y;

    int inc_take  = kh < cin ? kh : cin;
    int remaining = (inc_take > 0) ? (k - inc_take) : k;
    int out_take  = remaining < cout ? remaining : cout;
    int n = inc_take + out_take;

    // --- selection ----------------------------------------------------------
    if (cin <= 32) {
        unsigned long long key = (lane < cin) ? ci.x : 0ull;
        int rank = 0;
#pragma unroll
        for (int j = 0; j < 32; ++j) {
            unsigned long long o = __shfl_sync(0xffffffffu, key, j);
            rank += (o > key);
        }
        if (lane < cin && rank < inc_take) s_types[wl][rank] = (int)ci.y;
    } else {
        warp_select_big(&g_cand_inc[(size_t)b * CAP], cin < CAP ? cin : CAP,
                        inc_take, s_types[wl], 0, lane);
    }
    if (cout <= 32) {
        unsigned long long key = (lane < cout) ? co.x : 0ull;
        int rank = 0;
#pragma unroll
        for (int j = 0; j < 32; ++j) {
            unsigned long long o = __shfl_sync(0xffffffffu, key, j);
            rank += (o > key);
        }
        if (lane < cout && rank < out_take) s_types[wl][inc_take + rank] = (int)co.y;
    } else {
        warp_select_big(&g_cand_out[(size_t)b * CAP], cout < CAP ? cout : CAP,
                        out_take, s_types[wl], inc_take, lane);
    }
    __syncwarp();

    if (lane == 0) ((int2*)g_cnt)[b] = make_int2(0, 0);   // restore invariant

    // --- aggregation: float4 per lane when D % 4 == 0 -----------------------
    float denom = fmaxf((float)n, 1.0f);
    if ((D & 3) == 0) {
        const float4* qw4  = (const float4*)qw;
        float4*       out4 = (float4*)out;
        int D4 = D >> 2;
        for (int c = lane; c < D4; c += 32) {
            float4 acc = make_float4(0.f, 0.f, 0.f, 0.f);
            for (int i = 0; i < n; ++i) {
                float4 v = qw4[(size_t)s_types[wl][i] * D4 + c];
                acc.x += v.x; acc.y += v.y; acc.z += v.z; acc.w += v.w;
            }
            out4[(size_t)b * D4 + c] = make_float4(acc.x / denom, acc.y / denom,
                                                   acc.z / denom, acc.w / denom);
        }
    } else {
        for (int c = lane; c < D; c += 32) {
            float sum = 0.0f;
            for (int i = 0; i < n; ++i)
                sum += qw[(size_t)s_types[wl][i] * D + c];
            out[(size_t)b * D + c] = sum / denom;
        }
    }
}

// ---------------------------------------------------------------------------
// Host launcher (graph-capturable: launches only; PDL edge between them).
// Inputs: entity_index, edge_src, edge_dst, edge_types, edge_times,
//         query_weight, k, num_nodes.
// ---------------------------------------------------------------------------
extern "C" void kernel_launch(void* const* d_in, const int* in_sizes, int n_in,
                              void* d_out, int out_size) {
    const int*   ent = (const int*)d_in[0];
    const int*   src = (const int*)d_in[1];
    const int*   dst = (const int*)d_in[2];
    const int*   typ = (const int*)d_in[3];
    const float* tim = (const float*)d_in[4];
    const float* qw  = (const float*)d_in[5];
    const int*   kp  = (const int*)d_in[6];
    const int*   nnp = (const int*)d_in[7];

    int B = in_sizes[0];
    int E = in_sizes[1];
    int D = (B > 0) ? (out_size / B) : 0;

    int nblk = (E / 4 + 255) / 256;
    if (nblk > 256) nblk = 256;
    if (nblk < 1)   nblk = 1;

    k_scan<<<nblk, 256>>>(src, dst, typ, tim, E, ent, B, nnp);

    // PDL launch: k_agg's launch/prologue overlaps k_scan's execution.
    cudaLaunchAttribute attrs[1];
    attrs[0].id = cudaLaunchAttributeProgrammaticStreamSerialization;
    attrs[0].val.programmaticStreamSerializationAllowed = 1;
    cudaLaunchConfig_t cfg = {};
    cfg.gridDim  = dim3((unsigned)((B + 7) / 8), 1, 1);
    cfg.blockDim = dim3(256, 1, 1);
    cfg.dynamicSmemBytes = 0;
    cfg.stream = 0;
    cfg.attrs = attrs;
    cfg.numAttrs = 1;
    cudaLaunchKernelEx(&cfg, k_agg, qw, (float*)d_out, B, D, kp);
}

// round 7
// speedup vs baseline: 1.1346x; 1.1346x over previous
#include <cuda_runtime.h>

// ---------------------------------------------------------------------------
// TypeGAT HICS, inverted formulation, v7.
//
//  k_scan : per-block SMEM hash (node -> entity); grid-stride int4 pass over
//           edges; hits push ONE fused 16B record {packed key, edge type}.
//  k_agg  : PDL-launched; 1 block / entity, 128 threads. Warps 0/1 do the
//           exact top-k with speculative lane loads + shfl ranking; all 128
//           threads gather query_weight with a FIXED-TRIP fully-unrolled
//           predicated loop (independent loads -> one memory round).
//
// Key packing preserves lax.top_k ordering: time desc, edge index asc.
// ---------------------------------------------------------------------------

#define MAX_B       4096
#define CAP         64
#define MAX_NODES   (1 << 20)
#define MAXK        32
#define HASH_SLOTS  4096
#define HASH_MASK   (HASH_SLOTS - 1)
#define EMPTY       0xFFFFFFFFu

__device__ int        g_cnt[2 * MAX_B];                 // zero at load; k_agg restores
__device__ ulonglong2 g_cand_inc[(size_t)MAX_B * CAP];  // {key, type}
__device__ ulonglong2 g_cand_out[(size_t)MAX_B * CAP];

__device__ __forceinline__ unsigned int hash_node(unsigned int node) {
    return (node * 2654435761u) >> 20;   // top 12 bits -> [0, 4096)
}

// Orderable key: (monotone float bits << 32) | ~edge_index.
// Max key == (largest time, smallest index) — matches lax.top_k tie-break.
__device__ __forceinline__ unsigned long long pack_key(float t, unsigned int e) {
    unsigned int tb = __float_as_uint(t);
    tb = (tb & 0x80000000u) ? ~tb : (tb | 0x80000000u);
    return ((unsigned long long)tb << 32) | (unsigned long long)(~e);
}

__device__ __forceinline__ bool probe_any(const unsigned int* s_tab, unsigned int node) {
    if (node >= (unsigned int)MAX_NODES) return false;
    unsigned int h = hash_node(node), v;
    while ((v = s_tab[h]) != EMPTY) {
        if ((v >> 12) == node) return true;
        h = (h + 1) & HASH_MASK;
    }
    return false;
}

__device__ __forceinline__ void probe_push(const unsigned int* s_tab, unsigned int node,
                                           unsigned long long key, int etype, int dir,
                                           ulonglong2* __restrict__ cand) {
    unsigned int h = hash_node(node), v;
    while ((v = s_tab[h]) != EMPTY) {
        if ((v >> 12) == node) {
            int b = (int)(v & 0xFFFu);
            int p = atomicAdd(&g_cnt[2 * b + dir], 1);
            if (p < CAP)
                cand[(size_t)b * CAP + p] =
                    make_ulonglong2(key, (unsigned long long)(unsigned int)etype);
        }
        h = (h + 1) & HASH_MASK;
    }
}

// ---------------------------------------------------------------------------
// Kernel 1: edge scan with per-block SMEM hash.
// ---------------------------------------------------------------------------
__global__ void k_scan(const int* __restrict__ src, const int* __restrict__ dst,
                       const int* __restrict__ etypes,
                       const float* __restrict__ times, int E,
                       const int* __restrict__ ent, int B,
                       const int* __restrict__ nn_ptr) {
    __shared__ unsigned int s_tab[HASH_SLOTS];
    for (int i = threadIdx.x; i < HASH_SLOTS; i += blockDim.x) s_tab[i] = EMPTY;
    __syncthreads();

    int nn = nn_ptr[0];
    if (nn > MAX_NODES) nn = MAX_NODES;
    for (int b = threadIdx.x; b < B && b < MAX_B; b += blockDim.x) {
        int node = ent[b];
        if (node >= 0 && node < nn) {
            unsigned int val = ((unsigned int)node << 12) | (unsigned int)b;
            unsigned int h = hash_node((unsigned int)node);
            while (atomicCAS(&s_tab[h], EMPTY, val) != EMPTY) h = (h + 1) & HASH_MASK;
        }
    }
    __syncthreads();

    int tid    = blockIdx.x * blockDim.x + threadIdx.x;
    int stride = gridDim.x * blockDim.x;
    int E4     = E >> 2;
    const int4* src4 = (const int4*)src;
    const int4* dst4 = (const int4*)dst;

    for (int i = tid; i < E4; i += stride) {
        int4 d4 = dst4[i];
        int4 s4 = src4[i];
        int e0 = i << 2;
#pragma unroll
        for (int j = 0; j < 4; ++j) {
            unsigned int d = (unsigned int)((j == 0) ? d4.x : (j == 1) ? d4.y : (j == 2) ? d4.z : d4.w);
            unsigned int s = (unsigned int)((j == 0) ? s4.x : (j == 1) ? s4.y : (j == 2) ? s4.z : s4.w);
            bool hd = probe_any(s_tab, d);
            bool hs = probe_any(s_tab, s);
            if (hd | hs) {
                int e = e0 + j;
                unsigned long long key = pack_key(times[e], (unsigned int)e);
                int ty = etypes[e];
                if (hd) probe_push(s_tab, d, key, ty, 0, g_cand_inc);
                if (hs) probe_push(s_tab, s, key, ty, 1, g_cand_out);
            }
        }
    }
    for (int e = (E4 << 2) + tid; e < E; e += stride) {
        unsigned int d = (unsigned int)dst[e];
        unsigned int s = (unsigned int)src[e];
        bool hd = probe_any(s_tab, d);
        bool hs = probe_any(s_tab, s);
        if (hd | hs) {
            unsigned long long key = pack_key(times[e], (unsigned int)e);
            int ty = etypes[e];
            if (hd) probe_push(s_tab, d, key, ty, 0, g_cand_inc);
            if (hs) probe_push(s_tab, s, key, ty, 1, g_cand_out);
        }
    }
}

// Fallback exact top-`take` for n > 32: iterative warp-max over the row.
__device__ __forceinline__ void warp_select_big(const ulonglong2* __restrict__ row,
                                                int n, int take,
                                                int* s_types, int off, int lane) {
    unsigned long long thresh = ~0ull;
    for (int r = 0; r < take; ++r) {
        unsigned long long bk = 0ull; int bt = 0;
        for (int i = lane; i < n && i < CAP; i += 32) {
            ulonglong2 c = row[i];
            if (c.x < thresh && c.x > bk) { bk = c.x; bt = (int)c.y; }
        }
#pragma unroll
        for (int o = 16; o; o >>= 1) {
            unsigned long long ok = __shfl_xor_sync(0xffffffffu, bk, o);
            int                ot = __shfl_xor_sync(0xffffffffu, bt, o);
            if (ok > bk) { bk = ok; bt = ot; }
        }
        if (lane == 0) s_types[off + r] = bt;
        thresh = bk;
    }
}

// ---------------------------------------------------------------------------
// Kernel 2: selection + masked mean. PDL-aware. One block per entity.
// ---------------------------------------------------------------------------
__global__ void __launch_bounds__(128)
k_agg(const float* __restrict__ qw, float* __restrict__ out, int B, int D,
      const int* __restrict__ k_ptr) {
    int b = blockIdx.x;

    __shared__ int s_types[MAXK];
    __shared__ int s_n;

    int tid = threadIdx.x, wid = tid >> 5, lane = tid & 31;

    // Prologue: harness inputs only.
    int k = k_ptr[0];
    if (k > MAXK) k = MAXK;
    if (k < 0)    k = 0;
    int kh = k >> 1;

    cudaGridDependencySynchronize();
    if (b >= B || b >= MAX_B) return;

    if (wid < 2) {
        const ulonglong2* row = (wid == 0) ? &g_cand_inc[(size_t)b * CAP]
                                           : &g_cand_out[(size_t)b * CAP];
        // Speculative parallel loads: candidate record + both counters.
        ulonglong2 c = row[lane];
        int2 cc = ((const int2*)g_cnt)[b];
        int cin = cc.x, cout = cc.y;

        int inc_take  = kh < cin ? kh : cin;
        int remaining = (inc_take > 0) ? (k - inc_take) : k;
        int out_take  = remaining < cout ? remaining : cout;

        int n_mine   = (wid == 0) ? cin : cout;
        int take     = (wid == 0) ? inc_take : out_take;
        int off      = (wid == 0) ? 0 : inc_take;

        if (n_mine <= 32) {
            unsigned long long key = (lane < n_mine) ? c.x : 0ull;
            int rank = 0;
#pragma unroll
            for (int j = 0; j < 32; ++j) {
                unsigned long long o = __shfl_sync(0xffffffffu, key, j);
                rank += (o > key);
            }
            if (lane < n_mine && rank < take) s_types[off + rank] = (int)c.y;
        } else {
            warp_select_big(row, n_mine < CAP ? n_mine : CAP, take,
                            s_types, off, lane);
        }

        if (wid == 0 && lane == 0) {
            s_n = inc_take + out_take;
            ((int2*)g_cnt)[b] = make_int2(0, 0);   // restore invariant
        }
    }
    __syncthreads();

    int n = s_n;
    float denom = fmaxf((float)n, 1.0f);

    for (int d = tid; d < D; d += blockDim.x) {
        float sum = 0.0f;
        // Fixed-trip, fully-unrolled, predicated gather: all loads independent,
        // one memory round. n <= k <= 16 in practice.
#pragma unroll
        for (int i = 0; i < 16; ++i) {
            float v = (i < n) ? qw[(size_t)s_types[i] * D + d] : 0.0f;
            sum += v;
        }
        // Safety net for impossible n > 16 (k <= 32).
        for (int i = 16; i < n; ++i)
            sum += qw[(size_t)s_types[i] * D + d];
        out[(size_t)b * D + d] = sum / denom;
    }
}

// ---------------------------------------------------------------------------
// Host launcher (graph-capturable: launches only; PDL edge between them).
// Inputs: entity_index, edge_src, edge_dst, edge_types, edge_times,
//         query_weight, k, num_nodes.
// ---------------------------------------------------------------------------
extern "C" void kernel_launch(void* const* d_in, const int* in_sizes, int n_in,
                              void* d_out, int out_size) {
    const int*   ent = (const int*)d_in[0];
    const int*   src = (const int*)d_in[1];
    const int*   dst = (const int*)d_in[2];
    const int*   typ = (const int*)d_in[3];
    const float* tim = (const float*)d_in[4];
    const float* qw  = (const float*)d_in[5];
    const int*   kp  = (const int*)d_in[6];
    const int*   nnp = (const int*)d_in[7];

    int B = in_sizes[0];
    int E = in_sizes[1];
    int D = (B > 0) ? (out_size / B) : 0;

    int nblk = (E / 4 + 255) / 256;
    if (nblk > 256) nblk = 256;
    if (nblk < 1)   nblk = 1;

    k_scan<<<nblk, 256>>>(src, dst, typ, tim, E, ent, B, nnp);

    // PDL launch: k_agg's launch/prologue overlaps k_scan's execution.
    cudaLaunchAttribute attrs[1];
    attrs[0].id = cudaLaunchAttributeProgrammaticStreamSerialization;
    attrs[0].val.programmaticStreamSerializationAllowed = 1;
    cudaLaunchConfig_t cfg = {};
    cfg.gridDim  = dim3((unsigned)B, 1, 1);
    cfg.blockDim = dim3(128, 1, 1);
    cfg.dynamicSmemBytes = 0;
    cfg.stream = 0;
    cfg.attrs = attrs;
    cfg.numAttrs = 1;
    cudaLaunchKernelEx(&cfg, k_agg, qw, (float*)d_out, B, D, kp);
}